// round 4
// baseline (speedup 1.0000x reference)
#include <cuda_runtime.h>

// PIF integrate-and-fire, closed form: s = clamp(floor(x + 0.5f), 0, 8).
// Pure HBM stream: 205.5 MB in + 205.5 MB out.
//
// R4 = R3 resubmitted (R3 hit an infra failure, never ran):
//  - Exact-fit unpredicated kernel when n4 % (256*VPT) == 0 (true here:
//    12845056 / 2048 = 6272): no ISETP/@P chains, fewer regs, LDGs issue at
//    the 4-cyc LDG->LDG floor.
//  - VPT 4 -> 8: deeper per-warp MLP (8 outstanding LDG.128).
//  - Predicated fallback kernel for other sizes (deterministic dispatch on
//    size only).

#define VPT 8  // float4s per thread

__global__ void __launch_bounds__(256)
pif_kernel_exact(const float4* __restrict__ x, float4* __restrict__ out) {
    int base = blockIdx.x * (256 * VPT) + threadIdx.x;

    float4 v[VPT];
#pragma unroll
    for (int k = 0; k < VPT; k++)
        v[k] = __ldcs(&x[base + k * 256]);

#pragma unroll
    for (int k = 0; k < VPT; k++) {
        float4 r;
        r.x = fminf(8.0f, fmaxf(0.0f, floorf(v[k].x + 0.5f)));
        r.y = fminf(8.0f, fmaxf(0.0f, floorf(v[k].y + 0.5f)));
        r.z = fminf(8.0f, fmaxf(0.0f, floorf(v[k].z + 0.5f)));
        r.w = fminf(8.0f, fmaxf(0.0f, floorf(v[k].w + 0.5f)));
        __stcs(&out[base + k * 256], r);
    }
}

__global__ void __launch_bounds__(256)
pif_kernel_guarded(const float4* __restrict__ x, float4* __restrict__ out, int n4) {
    int base = blockIdx.x * (256 * VPT) + threadIdx.x;

    float4 v[VPT];
    bool ok[VPT];
#pragma unroll
    for (int k = 0; k < VPT; k++) {
        int i = base + k * 256;
        ok[k] = i < n4;
        if (ok[k]) v[k] = __ldcs(&x[i]);
    }

#pragma unroll
    for (int k = 0; k < VPT; k++) {
        float4 r;
        r.x = fminf(8.0f, fmaxf(0.0f, floorf(v[k].x + 0.5f)));
        r.y = fminf(8.0f, fmaxf(0.0f, floorf(v[k].y + 0.5f)));
        r.z = fminf(8.0f, fmaxf(0.0f, floorf(v[k].z + 0.5f)));
        r.w = fminf(8.0f, fmaxf(0.0f, floorf(v[k].w + 0.5f)));
        if (ok[k]) __stcs(&out[base + k * 256], r);
    }
}

// Tail for out_size % 4 != 0 (not hit here).
__global__ void pif_tail_kernel(const float* __restrict__ x, float* __restrict__ out,
                                int start, int n) {
    int i = start + blockIdx.x * blockDim.x + threadIdx.x;
    if (i < n) {
        out[i] = fminf(8.0f, fmaxf(0.0f, floorf(x[i] + 0.5f)));
    }
}

extern "C" void kernel_launch(void* const* d_in, const int* in_sizes, int n_in,
                              void* d_out, int out_size) {
    const float* x = (const float*)d_in[0];
    float* out = (float*)d_out;
    int n = out_size;

    int n4 = n / 4;
    const int threads = 256;
    const int epb = threads * VPT;  // 2048 float4s per block
    if (n4 > 0) {
        if (n4 % epb == 0) {
            pif_kernel_exact<<<n4 / epb, threads>>>((const float4*)x, (float4*)out);
        } else {
            pif_kernel_guarded<<<(n4 + epb - 1) / epb, threads>>>(
                (const float4*)x, (float4*)out, n4);
        }
    }
    int rem = n - n4 * 4;
    if (rem > 0) {
        pif_tail_kernel<<<1, 256>>>(x, out, n4 * 4, n);
    }
}